// round 1
// baseline (speedup 1.0000x reference)
#include <cuda_runtime.h>
#include <math.h>
#include <stdint.h>

#define Bb 16
#define Cc 32
#define Hh 128
#define Ww 128
#define HW 16384
#define Rr 8
#define OUTC 32

// ---------------- scratch (device globals; no allocation) ----------------
__device__ float d_pooled[Bb * Cc * 9];            // [b][c][kl]
__device__ float d_g[Bb * 64 * 9];                 // [b][rr][kl]
__device__ float d_kern[Bb * Rr * 288 * 32];       // [b][r][ckl][oo]  (ckl = c*9+kl)
__device__ int            d_cnt[Bb * Rr];          // per-list entry counts
__device__ unsigned short d_list[Bb * Rr * HW];    // entries: pix | flags<<14
__device__ float d_cat[(size_t)Bb * HW * 64];      // channel-last [b][pix][64] (spa 0..31, spec 32..63)
__device__ float d_wft[9 * 64 * 32];               // [kl][ch][o] transposed fusion weights

// ---------------- stage A1: adaptive avg pool 3x3 (torch bin edges) ----------------
__global__ void pool_kernel(const float* __restrict__ in) {
    int bc = blockIdx.x;                       // b*32+c
    const float* img = in + (size_t)bc * HW;
    __shared__ float red[256];
    int t = threadIdx.x;
    const int s0[3] = {0, 42, 85};
    const int e0[3] = {43, 86, 128};
    for (int by = 0; by < 3; by++) {
        for (int bx = 0; bx < 3; bx++) {
            int h0 = s0[by], h1 = e0[by], w0 = s0[bx], w1 = e0[bx];
            int nw = w1 - w0;
            int n = (h1 - h0) * nw;
            float sum = 0.f;
            for (int i = t; i < n; i += 256) {
                int yy = h0 + i / nw, xx = w0 + i % nw;
                sum += img[yy * Ww + xx];
            }
            red[t] = sum;
            __syncthreads();
            for (int o = 128; o > 0; o >>= 1) {
                if (t < o) red[t] += red[t + o];
                __syncthreads();
            }
            if (t == 0) d_pooled[bc * 9 + by * 3 + bx] = red[0] / (float)n;
            __syncthreads();
        }
    }
}

// ---------------- stage A2: gate g = sigmoid(w1 @ pooled + b1) ----------------
__global__ void g_kernel(const float* __restrict__ w1, const float* __restrict__ b1) {
    int idx = blockIdx.x * blockDim.x + threadIdx.x;
    if (idx >= Bb * 64 * 9) return;
    int kl = idx % 9;
    int rr = (idx / 9) % 64;
    int b  = idx / (64 * 9);
    float s = b1[rr];
    #pragma unroll
    for (int c = 0; c < Cc; c++)
        s += d_pooled[(b * Cc + c) * 9 + kl] * w1[rr * Cc + c];
    d_g[idx] = 1.f / (1.f + expf(-s));
}

// ---------------- stage A3: dynamic kernels ----------------
// kern[b][r][oo][c][kl] = b2[r*1024+oo*32+c] + sum_i g[b][r*8+i][kl] * w2[(r*1024+oo*32+c)*8+i]
// stored as d_kern[((b*8+r)*288 + c*9+kl)*32 + oo]
__global__ void kern_kernel(const float* __restrict__ w2, const float* __restrict__ b2) {
    int idx = blockIdx.x * blockDim.x + threadIdx.x;
    if (idx >= Bb * Rr * 288 * 32) return;
    int oo  = idx & 31;
    int t   = idx >> 5;
    int ckl = t % 288;
    int t2  = t / 288;
    int r   = t2 & 7;
    int b   = t2 >> 3;
    int c   = ckl / 9;
    int kl  = ckl % 9;
    int j   = r * 1024 + oo * 32 + c;
    float v = b2[j];
    #pragma unroll
    for (int i = 0; i < 8; i++)
        v += d_g[(b * 64 + r * 8 + i) * 9 + kl] * w2[j * 8 + i];
    d_kern[idx] = v;
}

// ---------------- zero counters ----------------
__global__ void zero_cnt_kernel() {
    int t = threadIdx.x;
    if (t < Bb * Rr) d_cnt[t] = 0;
}

// ---------------- stage B: per-pixel region argmax + list compaction ----------------
__global__ void __launch_bounds__(256) select_kernel(
    const float* __restrict__ guide,
    const float* __restrict__ w_spa, const float* __restrict__ b_spa,
    const float* __restrict__ w_spec, const float* __restrict__ b_spec) {
    int t = threadIdx.x;
    int b = blockIdx.y;
    int pix = blockIdx.x * 256 + t;

    float gv[Cc];
    #pragma unroll
    for (int c = 0; c < Cc; c++)
        gv[c] = __ldg(guide + ((size_t)(b * Cc + c)) * HW + pix);

    float best1 = -1e30f, best2 = -1e30f;
    int r1 = 0, r2 = 0;
    for (int r = 0; r < Rr; r++) {
        float s1 = __ldg(b_spa + r), s2 = __ldg(b_spec + r);
        #pragma unroll
        for (int c = 0; c < Cc; c++) {
            float w1v = __ldg(w_spa + r * Cc + c);
            float w2v = __ldg(w_spec + r * Cc + c);
            s1 += gv[c] * w1v;
            s2 += gv[c] * w2v;
        }
        if (s1 > best1) { best1 = s1; r1 = r; }
        if (s2 > best2) { best2 = s2; r2 = r; }
    }

    __shared__ int scnt[Rr];
    __shared__ int gbase[Rr];
    if (t < Rr) scnt[t] = 0;
    __syncthreads();

    int la = -1, lb = -1, sa = 0, sb = 0;
    unsigned short ea = 0, eb = 0;
    if (r1 == r2) {
        la = r1; ea = (unsigned short)(pix | (3 << 14));
        sa = atomicAdd(&scnt[la], 1);
    } else {
        la = r1; ea = (unsigned short)(pix | (1 << 14));
        sa = atomicAdd(&scnt[la], 1);
        lb = r2; eb = (unsigned short)(pix | (2 << 14));
        sb = atomicAdd(&scnt[lb], 1);
    }
    __syncthreads();
    if (t < Rr) gbase[t] = atomicAdd(&d_cnt[b * Rr + t], scnt[t]);
    __syncthreads();

    d_list[(b * Rr + la) * HW + gbase[la] + sa] = ea;
    if (lb >= 0)
        d_list[(b * Rr + lb) * HW + gbase[lb] + sb] = eb;
}

// ---------------- fusion weight transpose: wft[kl][ch][o] ----------------
__global__ void wf_prep_kernel(const float* __restrict__ wf) {
    int idx = blockIdx.x * blockDim.x + threadIdx.x;
    if (idx >= 9 * 64 * 32) return;
    int o  = idx & 31;
    int t  = idx >> 5;
    int ch = t & 63;
    int kl = t >> 6;
    d_wft[idx] = wf[(o * 64 + ch) * 9 + kl];
}

// ---------------- stage C: selected-region dynamic conv ----------------
// grid (32 slices, 8 regions, 16 batches), block 256 (8 warps).
// warp: 8 pixels x 4 oo-groups (8 oo each). kernel slab in smem [ckl][oo].
__global__ void __launch_bounds__(256) dynconv_kernel(const float* __restrict__ in) {
    int b = blockIdx.z, r = blockIdx.y, slice = blockIdx.x;
    int count = d_cnt[b * Rr + r];
    int e0 = slice * 512;
    if (e0 >= count) return;

    __shared__ float ks[288 * 32];
    {
        const float* kg = d_kern + (size_t)(b * Rr + r) * 288 * 32;
        for (int i = threadIdx.x; i < 288 * 32; i += 256) ks[i] = kg[i];
    }
    __syncthreads();

    int w = threadIdx.x >> 5, lane = threadIdx.x & 31;
    int g = lane >> 3, p = lane & 7;
    const float* inb = in + (size_t)b * Cc * HW;
    const unsigned short* lst = d_list + (b * Rr + r) * HW;

    for (int it = 0; it < 8; it++) {
        int e = e0 + (w * 8 + it) * 8 + p;
        int ent = (e < count) ? (int)lst[e] : 0;
        int flags = (e < count) ? (ent >> 14) : 0;
        int pix = ent & 0x3FFF;
        int y = pix >> 7, x = pix & 127;
        bool rtop = (y > 0), rbot = (y < Hh - 1);
        bool clft = (x > 0), crgt = (x < Ww - 1);

        float acc[8];
        #pragma unroll
        for (int u = 0; u < 8; u++) acc[u] = 0.f;

        const float* ip = inb + (long)(y - 1) * Ww + (x - 1);
        for (int c = 0; c < Cc; c++, ip += HW) {
            int cb = c * 9;
            #pragma unroll
            for (int ky = 0; ky < 3; ky++) {
                bool rv = (ky == 0) ? rtop : ((ky == 2) ? rbot : true);
                #pragma unroll
                for (int kx = 0; kx < 3; kx++) {
                    bool cv = (kx == 0) ? clft : ((kx == 2) ? crgt : true);
                    float v = (rv && cv) ? __ldg(ip + ky * Ww + kx) : 0.f;
                    const float4* kp = (const float4*)&ks[(cb + ky * 3 + kx) * 32 + g * 8];
                    float4 k0 = kp[0];
                    float4 k1 = kp[1];
                    acc[0] += v * k0.x; acc[1] += v * k0.y;
                    acc[2] += v * k0.z; acc[3] += v * k0.w;
                    acc[4] += v * k1.x; acc[5] += v * k1.y;
                    acc[6] += v * k1.z; acc[7] += v * k1.w;
                }
            }
        }

        float* cp = d_cat + ((size_t)(b * HW + pix)) * 64 + g * 8;
        float4 v0 = make_float4(acc[0], acc[1], acc[2], acc[3]);
        float4 v1 = make_float4(acc[4], acc[5], acc[6], acc[7]);
        if (flags & 1) {
            ((float4*)cp)[0] = v0;
            ((float4*)cp)[1] = v1;
        }
        if (flags & 2) {
            ((float4*)(cp + 32))[0] = v0;
            ((float4*)(cp + 32))[1] = v1;
        }
    }
}

// ---------------- stage D: fusion conv 3x3 (64->32) + bias + residual ----------------
// grid (2, 128, 16), block 256: warp = 8 consecutive x pixels, 4 oo-groups.
__global__ void __launch_bounds__(256) fusion_kernel(
    const float* __restrict__ in, const float* __restrict__ b_f,
    float* __restrict__ out) {
    int tid = threadIdx.x;
    int w = tid >> 5, lane = tid & 31;
    int g = lane >> 3, p = lane & 7;
    int x = blockIdx.x * 64 + w * 8 + p;
    int y = blockIdx.y;
    int b = blockIdx.z;

    float acc[8];
    #pragma unroll
    for (int u = 0; u < 8; u++) acc[u] = 0.f;

    const float* catb = d_cat + (size_t)b * HW * 64;
    #pragma unroll
    for (int ky = 0; ky < 3; ky++) {
        int yy = y + ky - 1;
        bool rv = ((unsigned)yy < (unsigned)Hh);
        #pragma unroll
        for (int kx = 0; kx < 3; kx++) {
            int xx = x + kx - 1;
            bool ok = rv && ((unsigned)xx < (unsigned)Ww);
            const float* cp = catb + (long)(yy * Ww + xx) * 64;
            const float* wp = d_wft + (ky * 3 + kx) * 64 * 32 + g * 8;
            #pragma unroll 8
            for (int ch = 0; ch < 64; ch++) {
                float v = ok ? __ldg(cp + ch) : 0.f;
                float4 k0 = __ldg((const float4*)(wp + ch * 32));
                float4 k1 = __ldg((const float4*)(wp + ch * 32 + 4));
                acc[0] += v * k0.x; acc[1] += v * k0.y;
                acc[2] += v * k0.z; acc[3] += v * k0.w;
                acc[4] += v * k1.x; acc[5] += v * k1.y;
                acc[6] += v * k1.z; acc[7] += v * k1.w;
            }
        }
    }

    long pixoff = (long)y * Ww + x;
    #pragma unroll
    for (int u = 0; u < 8; u++) {
        int o = g * 8 + u;
        long idx = ((long)(b * Cc + o)) * HW + pixoff;
        out[idx] = acc[u] + __ldg(b_f + o) + __ldg(in + idx);
    }
}

// ---------------- launch ----------------
extern "C" void kernel_launch(void* const* d_in, const int* in_sizes, int n_in,
                              void* d_out, int out_size) {
    const float* input  = (const float*)d_in[0];
    const float* guide  = (const float*)d_in[1];
    const float* w1     = (const float*)d_in[2];
    const float* b1     = (const float*)d_in[3];
    const float* w2     = (const float*)d_in[4];
    const float* b2     = (const float*)d_in[5];
    const float* w_spa  = (const float*)d_in[6];
    const float* b_spa  = (const float*)d_in[7];
    const float* w_spec = (const float*)d_in[8];
    const float* b_spec = (const float*)d_in[9];
    const float* w_f    = (const float*)d_in[10];
    const float* b_f    = (const float*)d_in[11];
    float* out = (float*)d_out;

    pool_kernel<<<Bb * Cc, 256>>>(input);
    g_kernel<<<(Bb * 64 * 9 + 255) / 256, 256>>>(w1, b1);
    kern_kernel<<<(Bb * Rr * 288 * 32 + 255) / 256, 256>>>(w2, b2);
    zero_cnt_kernel<<<1, 128>>>();
    select_kernel<<<dim3(HW / 256, Bb), 256>>>(guide, w_spa, b_spa, w_spec, b_spec);
    wf_prep_kernel<<<(9 * 64 * 32 + 255) / 256, 256>>>(w_f);
    dynconv_kernel<<<dim3(32, Rr, Bb), 256>>>(input);
    fusion_kernel<<<dim3(2, Hh, Bb), 256>>>(input, b_f, out);
}